// round 3
// baseline (speedup 1.0000x reference)
#include <cuda_runtime.h>
#include <cstdint>

#define N_NODES   100000
#define DIM       512
#define TILE_M    64
#define KC        32                 // K floats per chunk (128B per row)
#define N_CHUNKS  16
#define THREADS   256
#define NUM_TILES ((N_NODES + TILE_M - 1) / TILE_M)   // 1563

// SMEM rows padded to 160B (40 words, 40 % 32 == 8) -> conflict-free LDS.64
#define ROW_BYTES   160
#define A_BYTES     (TILE_M * ROW_BYTES)      // 10240
#define B_BYTES     (512 * ROW_BYTES)         // 81920
#define STAGE_BYTES (A_BYTES + B_BYTES)       // 92160

#define SM_BIAS   0
#define SM_GAMMA  2048
#define SM_BETA   4096
#define SM_RSUM   6144                        // [64][8] f32
#define SM_RSQ    8192                        // [64][8] f32
#define SM_MEAN   10240                       // [64] f32
#define SM_RSTD   10496                       // [64] f32
#define SM_STAGE  11264                       // 1024-aligned
#define SMEM_TOTAL (SM_STAGE + 2 * STAGE_BYTES)   // 195584

#define OUT_STRIDE_W 520                      // epilogue staging stride (words)

static __device__ __forceinline__ uint32_t smem_u32(const void* p) {
    uint32_t a;
    asm("{ .reg .u64 t; cvta.to.shared.u64 t, %1; cvt.u32.u64 %0, t; }" : "=r"(a) : "l"(p));
    return a;
}

static __device__ __forceinline__ uint2 lds64(uint32_t a) {
    uint2 v;
    asm volatile("ld.shared.v2.b32 {%0, %1}, [%2];" : "=r"(v.x), "=r"(v.y) : "r"(a));
    return v;
}

static __device__ __forceinline__ void mma_tf32(float* d, uint2 alo, uint2 ahi, uint2 b) {
    // logical k relabeled to physical columns: a0/b0 <- .x (col 2q), a2/b1 <- .y (col 2q+1)
    asm volatile(
        "mma.sync.aligned.m16n8k8.row.col.f32.tf32.tf32.f32 "
        "{%0,%1,%2,%3}, {%4,%5,%6,%7}, {%8,%9}, {%0,%1,%2,%3};"
        : "+f"(d[0]), "+f"(d[1]), "+f"(d[2]), "+f"(d[3])
        : "r"(alo.x), "r"(ahi.x), "r"(alo.y), "r"(ahi.y), "r"(b.x), "r"(b.y));
}

static __device__ __forceinline__ void cp16(uint32_t dst, const void* src) {
    asm volatile("cp.async.cg.shared.global [%0], [%1], 16;" :: "r"(dst), "l"(src));
}

// Load one K-chunk: A 64x32f, B 512x32f into stage (rows padded to 160B)
static __device__ __forceinline__ void load_chunk(const float* __restrict__ x,
                                                  const float* __restrict__ W,
                                                  int m0, int kc, uint32_t stage,
                                                  int tid) {
    const uint32_t a_base = stage;
    const uint32_t b_base = stage + A_BYTES;
    const int kcol = kc * KC;
#pragma unroll
    for (int it = 0; it < 2; it++) {                 // A: 512 granules
        int id  = it * THREADS + tid;
        int row = id >> 3, j = id & 7;
        int gr  = m0 + row;
        if (gr > N_NODES - 1) gr = N_NODES - 1;      // clamp; garbage rows never stored
        cp16(a_base + (uint32_t)(row * ROW_BYTES + j * 16),
             x + (size_t)gr * DIM + kcol + j * 4);
    }
#pragma unroll
    for (int it = 0; it < 16; it++) {                // B: 4096 granules
        int id  = it * THREADS + tid;
        int row = id >> 3, j = id & 7;
        cp16(b_base + (uint32_t)(row * ROW_BYTES + j * 16),
             W + (size_t)row * DIM + kcol + j * 4);
    }
}

__global__ void __launch_bounds__(THREADS, 1)
fused_gemm_ln_lrelu(const float* __restrict__ x, const float* __restrict__ W,
                    const float* __restrict__ bias, const float* __restrict__ gamma,
                    const float* __restrict__ beta, float* __restrict__ out) {
    extern __shared__ __align__(1024) char smem[];
    const uint32_t sb = smem_u32(smem);
    const int tid  = threadIdx.x;
    const int lane = tid & 31;
    const int wid  = tid >> 5;
    const int q    = lane & 3;       // thread-in-group
    const int g    = lane >> 2;      // group id
    const int m0   = blockIdx.x * TILE_M;

    // params into smem
#pragma unroll
    for (int i = 0; i < 2; i++) {
        int c = i * THREADS + tid;
        ((float*)(smem + SM_BIAS))[c]  = bias[c];
        ((float*)(smem + SM_GAMMA))[c] = gamma[c];
        ((float*)(smem + SM_BETA))[c]  = beta[c];
    }

    float acc[4][8][4];
#pragma unroll
    for (int mt = 0; mt < 4; mt++)
#pragma unroll
        for (int nt = 0; nt < 8; nt++)
#pragma unroll
            for (int u = 0; u < 4; u++) acc[mt][nt][u] = 0.f;

    // prologue
    load_chunk(x, W, m0, 0, sb + SM_STAGE, tid);
    asm volatile("cp.async.commit_group;" ::: "memory");

    const uint32_t wb = (uint32_t)wid * 64;   // warp n-base

#pragma unroll 1
    for (int i = 0; i < N_CHUNKS; i++) {
        if (i + 1 < N_CHUNKS) {
            load_chunk(x, W, m0, i + 1, sb + SM_STAGE + (uint32_t)((i + 1) & 1) * STAGE_BYTES, tid);
            asm volatile("cp.async.commit_group;" ::: "memory");
            asm volatile("cp.async.wait_group 1;" ::: "memory");
        } else {
            asm volatile("cp.async.wait_group 0;" ::: "memory");
        }
        __syncthreads();

        const uint32_t SA = sb + SM_STAGE + (uint32_t)(i & 1) * STAGE_BYTES;
        const uint32_t SB = SA + A_BYTES;
#pragma unroll
        for (int ks = 0; ks < 4; ks++) {
            const uint32_t kb = (uint32_t)(ks * 32 + q * 8);
            uint2 alo[4], ahi[4];
#pragma unroll
            for (int mt = 0; mt < 4; mt++) {
                uint32_t ar = SA + (uint32_t)((16 * mt + g) * ROW_BYTES) + kb;
                alo[mt] = lds64(ar);
                ahi[mt] = lds64(ar + 8 * ROW_BYTES);
            }
            uint2 bf[8];
#pragma unroll
            for (int nt = 0; nt < 8; nt++)
                bf[nt] = lds64(SB + (wb + 8 * nt + (uint32_t)g) * ROW_BYTES + kb);
#pragma unroll
            for (int mt = 0; mt < 4; mt++)
#pragma unroll
                for (int nt = 0; nt < 8; nt++)
                    mma_tf32(acc[mt][nt], alo[mt], ahi[mt], bf[nt]);
        }
        __syncthreads();
    }

    // ---------------- epilogue ----------------
    const float* bs = (const float*)(smem + SM_BIAS);
    const float* gs = (const float*)(smem + SM_GAMMA);
    const float* es = (const float*)(smem + SM_BETA);
    float* rsum = (float*)(smem + SM_RSUM);
    float* rsq  = (float*)(smem + SM_RSQ);
    float* smean = (float*)(smem + SM_MEAN);
    float* srstd = (float*)(smem + SM_RSTD);

    // bias add (in-register)
#pragma unroll
    for (int nt = 0; nt < 8; nt++) {
        int c0 = (int)wb + 8 * nt + 2 * q;
        float b0 = bs[c0], b1 = bs[c0 + 1];
#pragma unroll
        for (int mt = 0; mt < 4; mt++) {
            acc[mt][nt][0] += b0; acc[mt][nt][1] += b1;
            acc[mt][nt][2] += b0; acc[mt][nt][3] += b1;
        }
    }

    // per-row partial sums (rows 16mt+g and 16mt+8+g)
    float sA[4], qA[4], sB[4], qB[4];
#pragma unroll
    for (int mt = 0; mt < 4; mt++) {
        float s0 = 0.f, q0 = 0.f, s1 = 0.f, q1 = 0.f;
#pragma unroll
        for (int nt = 0; nt < 8; nt++) {
            float v0 = acc[mt][nt][0], v1 = acc[mt][nt][1];
            float v2 = acc[mt][nt][2], v3 = acc[mt][nt][3];
            s0 += v0 + v1;  q0 += v0 * v0 + v1 * v1;
            s1 += v2 + v3;  q1 += v2 * v2 + v3 * v3;
        }
        sA[mt] = s0; qA[mt] = q0; sB[mt] = s1; qB[mt] = q1;
    }
    // quad reduce (lanes sharing g)
#pragma unroll
    for (int off = 1; off <= 2; off <<= 1) {
#pragma unroll
        for (int mt = 0; mt < 4; mt++) {
            sA[mt] += __shfl_xor_sync(0xffffffffu, sA[mt], off);
            qA[mt] += __shfl_xor_sync(0xffffffffu, qA[mt], off);
            sB[mt] += __shfl_xor_sync(0xffffffffu, sB[mt], off);
            qB[mt] += __shfl_xor_sync(0xffffffffu, qB[mt], off);
        }
    }
    if (q == 0) {
#pragma unroll
        for (int mt = 0; mt < 4; mt++) {
            rsum[(16 * mt + g) * 8 + wid]     = sA[mt];
            rsq [(16 * mt + g) * 8 + wid]     = qA[mt];
            rsum[(16 * mt + 8 + g) * 8 + wid] = sB[mt];
            rsq [(16 * mt + 8 + g) * 8 + wid] = qB[mt];
        }
    }
    __syncthreads();

    if (tid < 64) {
        float s = 0.f, ss = 0.f;
#pragma unroll
        for (int w = 0; w < 8; w++) { s += rsum[tid * 8 + w]; ss += rsq[tid * 8 + w]; }
        float mean = s * (1.0f / 512.0f);
        float var  = ss * (1.0f / 512.0f) - mean * mean;
        smean[tid] = mean;
        srstd[tid] = rsqrtf(var + 1e-5f);
    }
    __syncthreads();

    // normalize + LeakyReLU -> padded smem staging (reuses stage region)
    const uint32_t OS = sb + SM_STAGE;
#pragma unroll
    for (int mt = 0; mt < 4; mt++) {
        int rA = 16 * mt + g, rB = rA + 8;
        float mA = smean[rA], rsdA = srstd[rA];
        float mB = smean[rB], rsdB = srstd[rB];
#pragma unroll
        for (int nt = 0; nt < 8; nt++) {
            int c0 = (int)wb + 8 * nt + 2 * q;
            float g0 = gs[c0], g1 = gs[c0 + 1];
            float e0 = es[c0], e1 = es[c0 + 1];
            float t0 = (acc[mt][nt][0] - mA) * rsdA * g0 + e0;
            float t1 = (acc[mt][nt][1] - mA) * rsdA * g1 + e1;
            float t2 = (acc[mt][nt][2] - mB) * rsdB * g0 + e0;
            float t3 = (acc[mt][nt][3] - mB) * rsdB * g1 + e1;
            t0 = fmaxf(t0, 0.2f * t0);
            t1 = fmaxf(t1, 0.2f * t1);
            t2 = fmaxf(t2, 0.2f * t2);
            t3 = fmaxf(t3, 0.2f * t3);
            uint32_t a0 = OS + (uint32_t)(rA * OUT_STRIDE_W + c0) * 4;
            uint32_t a1 = OS + (uint32_t)(rB * OUT_STRIDE_W + c0) * 4;
            asm volatile("st.shared.v2.f32 [%0], {%1, %2};" :: "r"(a0), "f"(t0), "f"(t1) : "memory");
            asm volatile("st.shared.v2.f32 [%0], {%1, %2};" :: "r"(a1), "f"(t2), "f"(t3) : "memory");
        }
    }
    __syncthreads();

    // coalesced writeback: 64 rows x 512 floats = 8192 float4s, 256 threads -> 32 iters
#pragma unroll
    for (int it = 0; it < 32; it++) {
        int id  = it * THREADS + tid;
        int row = id >> 7;          // 128 float4 per row
        int j   = id & 127;
        int gr  = m0 + row;
        if (gr < N_NODES) {
            uint32_t a = OS + (uint32_t)(row * OUT_STRIDE_W + j * 4) * 4;
            uint32_t v0, v1, v2, v3;
            asm volatile("ld.shared.v4.b32 {%0, %1, %2, %3}, [%4];"
                         : "=r"(v0), "=r"(v1), "=r"(v2), "=r"(v3) : "r"(a));
            float4 o;
            o.x = __uint_as_float(v0); o.y = __uint_as_float(v1);
            o.z = __uint_as_float(v2); o.w = __uint_as_float(v3);
            *(float4*)(out + (size_t)gr * DIM + j * 4) = o;
        }
    }
}

extern "C" void kernel_launch(void* const* d_in, const int* in_sizes, int n_in,
                              void* d_out, int out_size) {
    const float* x     = (const float*)d_in[0];
    // d_in[1] edge_attr, d_in[2] edge_index, d_in[3] batch: dead inputs
    const float* W     = (const float*)d_in[4];
    const float* bias  = (const float*)d_in[5];
    const float* gamma = (const float*)d_in[6];
    const float* beta  = (const float*)d_in[7];
    float* out = (float*)d_out;

    cudaFuncSetAttribute(fused_gemm_ln_lrelu,
                         cudaFuncAttributeMaxDynamicSharedMemorySize, SMEM_TOTAL);
    fused_gemm_ln_lrelu<<<NUM_TILES, THREADS, SMEM_TOTAL>>>(x, W, bias, gamma, beta, out);
}

// round 4
// speedup vs baseline: 1.4854x; 1.4854x over previous
#include <cuda_runtime.h>
#include <cuda_fp16.h>
#include <cstdint>

#define N_NODES   100000
#define DIM       512
#define TILE_M    64
#define KCH       64                 // K elems per chunk (64 halfs = 128B data row)
#define N_CHUNKS  8
#define THREADS   256
#define NUM_TILES ((N_NODES + TILE_M - 1) / TILE_M)   // 1563

// SMEM rows: 128B fp16 data padded to 160B (40 words) -> conflict-free LDS.64
#define ROW_BYTES   160
#define A_BYTES     (TILE_M * ROW_BYTES)      // 10240
#define B_BYTES     (512 * ROW_BYTES)         // 81920
#define STAGE_BYTES (A_BYTES + B_BYTES)       // 92160

#define SM_BIAS   0
#define SM_GAMMA  2048
#define SM_BETA   4096
#define SM_RSUM   6144                        // [64][8] f32
#define SM_RSQ    8192                        // [64][8] f32
#define SM_MEAN   10240
#define SM_RSTD   10496
#define SM_STAGE  11264                       // 1024-aligned
#define SMEM_TOTAL (SM_STAGE + 2 * STAGE_BYTES)   // 195584

#define OUT_STRIDE_W 520                      // epilogue staging stride (words)

__device__ __half g_Wh[512 * 512];            // pre-converted W (512KB, L2-resident)

static __device__ __forceinline__ uint32_t smem_u32(const void* p) {
    uint32_t a;
    asm("{ .reg .u64 t; cvta.to.shared.u64 t, %1; cvt.u32.u64 %0, t; }" : "=r"(a) : "l"(p));
    return a;
}

static __device__ __forceinline__ uint2 lds64(uint32_t a) {
    uint2 v;
    asm volatile("ld.shared.v2.b32 {%0, %1}, [%2];" : "=r"(v.x), "=r"(v.y) : "r"(a));
    return v;
}

// m16n8k16 fp16 MMA; physical k cols 4q..4q+3 carry logical {2q,2q+1,2q+8,2q+9}
// (consistent A/B relabeling -> dot product invariant).
// a0=lo.x(row g), a1=hi.x(row g+8), a2=lo.y, a3=hi.y ; b0=b.x, b1=b.y
static __device__ __forceinline__ void mma_f16(float* d, uint2 lo, uint2 hi, uint2 b) {
    asm volatile(
        "mma.sync.aligned.m16n8k16.row.col.f32.f16.f16.f32 "
        "{%0,%1,%2,%3}, {%4,%5,%6,%7}, {%8,%9}, {%0,%1,%2,%3};"
        : "+f"(d[0]), "+f"(d[1]), "+f"(d[2]), "+f"(d[3])
        : "r"(lo.x), "r"(hi.x), "r"(lo.y), "r"(hi.y), "r"(b.x), "r"(b.y));
}

static __device__ __forceinline__ void cp16(uint32_t dst, const void* src) {
    asm volatile("cp.async.cg.shared.global [%0], [%1], 16;" :: "r"(dst), "l"(src));
}

// B chunk: 512 rows x 128B fp16 from g_Wh into stage (160B padded rows)
static __device__ __forceinline__ void load_B(int kc, uint32_t b_base, int tid) {
#pragma unroll
    for (int it = 0; it < 16; it++) {
        int id  = it * THREADS + tid;
        int row = id >> 3, j = id & 7;
        cp16(b_base + (uint32_t)(row * ROW_BYTES + j * 16),
             g_Wh + (size_t)row * DIM + kc * KCH + j * 8);
    }
}

// A chunk LDG: thread -> row tid>>2, 16 floats at col base (tid&3)*16
static __device__ __forceinline__ void ldg_A(const float* __restrict__ x,
                                             int m0, int kc, int tid, float4* r) {
    int row = tid >> 2;
    int gr  = m0 + row;
    if (gr > N_NODES - 1) gr = N_NODES - 1;   // clamped rows never stored
    const float* p = x + (size_t)gr * DIM + kc * KCH + (tid & 3) * 16;
    r[0] = *(const float4*)(p);
    r[1] = *(const float4*)(p + 4);
    r[2] = *(const float4*)(p + 8);
    r[3] = *(const float4*)(p + 12);
}

// convert + store A chunk regs into stage A region
static __device__ __forceinline__ void sts_A(uint32_t a_base, int tid, const float4* r) {
    uint32_t a = a_base + (uint32_t)((tid >> 2) * ROW_BYTES + (tid & 3) * 32);
    uint32_t h[8];
#pragma unroll
    for (int k = 0; k < 4; k++) {
        __half2 x0 = __floats2half2_rn(r[k].x, r[k].y);
        __half2 x1 = __floats2half2_rn(r[k].z, r[k].w);
        h[2 * k]     = *(uint32_t*)&x0;
        h[2 * k + 1] = *(uint32_t*)&x1;
    }
    asm volatile("st.shared.v4.b32 [%0], {%1,%2,%3,%4};" :: "r"(a),
                 "r"(h[0]), "r"(h[1]), "r"(h[2]), "r"(h[3]) : "memory");
    asm volatile("st.shared.v4.b32 [%0], {%1,%2,%3,%4};" :: "r"(a + 16),
                 "r"(h[4]), "r"(h[5]), "r"(h[6]), "r"(h[7]) : "memory");
}

__global__ void wconv_kernel(const float* __restrict__ W) {
    int i = (blockIdx.x * blockDim.x + threadIdx.x) * 4;
    float4 v = *(const float4*)(W + i);
    __half2 h0 = __floats2half2_rn(v.x, v.y);
    __half2 h1 = __floats2half2_rn(v.z, v.w);
    *(__half2*)(g_Wh + i)     = h0;
    *(__half2*)(g_Wh + i + 2) = h1;
}

__global__ void __launch_bounds__(THREADS, 1)
fused_gemm_ln_lrelu(const float* __restrict__ x,
                    const float* __restrict__ bias, const float* __restrict__ gamma,
                    const float* __restrict__ beta, float* __restrict__ out) {
    extern __shared__ __align__(1024) char smem[];
    const uint32_t sb = smem_u32(smem);
    const int tid  = threadIdx.x;
    const int lane = tid & 31;
    const int wid  = tid >> 5;
    const int q    = lane & 3;
    const int g    = lane >> 2;
    const int m0   = blockIdx.x * TILE_M;

#pragma unroll
    for (int i = 0; i < 2; i++) {
        int c = i * THREADS + tid;
        ((float*)(smem + SM_BIAS))[c]  = bias[c];
        ((float*)(smem + SM_GAMMA))[c] = gamma[c];
        ((float*)(smem + SM_BETA))[c]  = beta[c];
    }

    float acc[4][8][4];
#pragma unroll
    for (int mt = 0; mt < 4; mt++)
#pragma unroll
        for (int nt = 0; nt < 8; nt++)
#pragma unroll
            for (int u = 0; u < 4; u++) acc[mt][nt][u] = 0.f;

    const uint32_t st0 = sb + SM_STAGE;
    const uint32_t st1 = st0 + STAGE_BYTES;

    // prologue: A0 via LDG->cvt->STS ; B0, B1 via cp.async
    float4 r[4];
    ldg_A(x, m0, 0, tid, r);
    load_B(0, st0 + A_BYTES, tid);
    asm volatile("cp.async.commit_group;" ::: "memory");
    sts_A(st0, tid, r);
    ldg_A(x, m0, 1, tid, r);
    load_B(1, st1 + A_BYTES, tid);
    asm volatile("cp.async.commit_group;" ::: "memory");

    const uint32_t wb = (uint32_t)wid * 64;

#pragma unroll 1
    for (int i = 0; i < N_CHUNKS; i++) {
        const uint32_t SA  = (i & 1) ? st1 : st0;
        const uint32_t SAo = (i & 1) ? st0 : st1;   // other stage
        if (i < N_CHUNKS - 1) asm volatile("cp.async.wait_group 1;" ::: "memory");
        else                  asm volatile("cp.async.wait_group 0;" ::: "memory");
        __syncthreads();   // B(i)+A(i) visible; stage(other) fully consumed

        if (i + 1 < N_CHUNKS) {
            sts_A(SAo, tid, r);                 // A(i+1) into other stage
            if (i + 2 < N_CHUNKS) ldg_A(x, m0, i + 2, tid, r);
        }

        const uint32_t SBS = SA + A_BYTES;
#pragma unroll
        for (int s = 0; s < 4; s++) {
            const uint32_t kb = (uint32_t)(s * 32 + q * 8);
            uint2 alo[4], ahi[4];
#pragma unroll
            for (int mt = 0; mt < 4; mt++) {
                uint32_t ar = SA + (uint32_t)((16 * mt + g) * ROW_BYTES) + kb;
                alo[mt] = lds64(ar);
                ahi[mt] = lds64(ar + 8 * ROW_BYTES);
            }
            uint2 bf[8];
#pragma unroll
            for (int nt = 0; nt < 8; nt++)
                bf[nt] = lds64(SBS + (wb + 8 * nt + (uint32_t)g) * ROW_BYTES + kb);
#pragma unroll
            for (int mt = 0; mt < 4; mt++)
#pragma unroll
                for (int nt = 0; nt < 8; nt++)
                    mma_f16(acc[mt][nt], alo[mt], ahi[mt], bf[nt]);
        }
        __syncthreads();   // all warps done reading stage SA

        if (i + 2 < N_CHUNKS) {
            load_B(i + 2, SA + A_BYTES, tid);   // reuse just-freed stage
            asm volatile("cp.async.commit_group;" ::: "memory");
        }
    }

    // ---------------- epilogue (unchanged) ----------------
    const float* bs = (const float*)(smem + SM_BIAS);
    const float* gs = (const float*)(smem + SM_GAMMA);
    const float* es = (const float*)(smem + SM_BETA);
    float* rsum  = (float*)(smem + SM_RSUM);
    float* rsq   = (float*)(smem + SM_RSQ);
    float* smean = (float*)(smem + SM_MEAN);
    float* srstd = (float*)(smem + SM_RSTD);

#pragma unroll
    for (int nt = 0; nt < 8; nt++) {
        int c0 = (int)wb + 8 * nt + 2 * q;
        float b0 = bs[c0], b1 = bs[c0 + 1];
#pragma unroll
        for (int mt = 0; mt < 4; mt++) {
            acc[mt][nt][0] += b0; acc[mt][nt][1] += b1;
            acc[mt][nt][2] += b0; acc[mt][nt][3] += b1;
        }
    }

    float sA[4], qA[4], sB[4], qB[4];
#pragma unroll
    for (int mt = 0; mt < 4; mt++) {
        float s0 = 0.f, q0 = 0.f, s1 = 0.f, q1 = 0.f;
#pragma unroll
        for (int nt = 0; nt < 8; nt++) {
            float v0 = acc[mt][nt][0], v1 = acc[mt][nt][1];
            float v2 = acc[mt][nt][2], v3 = acc[mt][nt][3];
            s0 += v0 + v1;  q0 += v0 * v0 + v1 * v1;
            s1 += v2 + v3;  q1 += v2 * v2 + v3 * v3;
        }
        sA[mt] = s0; qA[mt] = q0; sB[mt] = s1; qB[mt] = q1;
    }
#pragma unroll
    for (int off = 1; off <= 2; off <<= 1) {
#pragma unroll
        for (int mt = 0; mt < 4; mt++) {
            sA[mt] += __shfl_xor_sync(0xffffffffu, sA[mt], off);
            qA[mt] += __shfl_xor_sync(0xffffffffu, qA[mt], off);
            sB[mt] += __shfl_xor_sync(0xffffffffu, sB[mt], off);
            qB[mt] += __shfl_xor_sync(0xffffffffu, qB[mt], off);
        }
    }
    if (q == 0) {
#pragma unroll
        for (int mt = 0; mt < 4; mt++) {
            rsum[(16 * mt + g) * 8 + wid]     = sA[mt];
            rsq [(16 * mt + g) * 8 + wid]     = qA[mt];
            rsum[(16 * mt + 8 + g) * 8 + wid] = sB[mt];
            rsq [(16 * mt + 8 + g) * 8 + wid] = qB[mt];
        }
    }
    __syncthreads();

    if (tid < 64) {
        float s = 0.f, ss = 0.f;
#pragma unroll
        for (int w = 0; w < 8; w++) { s += rsum[tid * 8 + w]; ss += rsq[tid * 8 + w]; }
        float mean = s * (1.0f / 512.0f);
        float var  = ss * (1.0f / 512.0f) - mean * mean;
        smean[tid] = mean;
        srstd[tid] = rsqrtf(var + 1e-5f);
    }
    __syncthreads();

    const uint32_t OS = sb + SM_STAGE;
#pragma unroll
    for (int mt = 0; mt < 4; mt++) {
        int rA = 16 * mt + g, rB = rA + 8;
        float mA = smean[rA], rsdA = srstd[rA];
        float mB = smean[rB], rsdB = srstd[rB];
#pragma unroll
        for (int nt = 0; nt < 8; nt++) {
            int c0 = (int)wb + 8 * nt + 2 * q;
            float g0 = gs[c0], g1 = gs[c0 + 1];
            float e0 = es[c0], e1 = es[c0 + 1];
            float t0 = (acc[mt][nt][0] - mA) * rsdA * g0 + e0;
            float t1 = (acc[mt][nt][1] - mA) * rsdA * g1 + e1;
            float t2 = (acc[mt][nt][2] - mB) * rsdB * g0 + e0;
            float t3 = (acc[mt][nt][3] - mB) * rsdB * g1 + e1;
            t0 = fmaxf(t0, 0.2f * t0);
            t1 = fmaxf(t1, 0.2f * t1);
            t2 = fmaxf(t2, 0.2f * t2);
            t3 = fmaxf(t3, 0.2f * t3);
            uint32_t a0 = OS + (uint32_t)(rA * OUT_STRIDE_W + c0) * 4;
            uint32_t a1 = OS + (uint32_t)(rB * OUT_STRIDE_W + c0) * 4;
            asm volatile("st.shared.v2.f32 [%0], {%1, %2};" :: "r"(a0), "f"(t0), "f"(t1) : "memory");
            asm volatile("st.shared.v2.f32 [%0], {%1, %2};" :: "r"(a1), "f"(t2), "f"(t3) : "memory");
        }
    }
    __syncthreads();

#pragma unroll
    for (int it = 0; it < 32; it++) {
        int id  = it * THREADS + tid;
        int row = id >> 7;
        int j   = id & 127;
        int gr  = m0 + row;
        if (gr < N_NODES) {
            uint32_t a = OS + (uint32_t)(row * OUT_STRIDE_W + j * 4) * 4;
            uint32_t v0, v1, v2, v3;
            asm volatile("ld.shared.v4.b32 {%0, %1, %2, %3}, [%4];"
                         : "=r"(v0), "=r"(v1), "=r"(v2), "=r"(v3) : "r"(a));
            float4 o;
            o.x = __uint_as_float(v0); o.y = __uint_as_float(v1);
            o.z = __uint_as_float(v2); o.w = __uint_as_float(v3);
            *(float4*)(out + (size_t)gr * DIM + j * 4) = o;
        }
    }
}

extern "C" void kernel_launch(void* const* d_in, const int* in_sizes, int n_in,
                              void* d_out, int out_size) {
    const float* x     = (const float*)d_in[0];
    // d_in[1] edge_attr, d_in[2] edge_index, d_in[3] batch: dead inputs
    const float* W     = (const float*)d_in[4];
    const float* bias  = (const float*)d_in[5];
    const float* gamma = (const float*)d_in[6];
    const float* beta  = (const float*)d_in[7];
    float* out = (float*)d_out;

    wconv_kernel<<<256, 256>>>(W);

    cudaFuncSetAttribute(fused_gemm_ln_lrelu,
                         cudaFuncAttributeMaxDynamicSharedMemorySize, SMEM_TOTAL);
    fused_gemm_ln_lrelu<<<NUM_TILES, THREADS, SMEM_TOTAL>>>(x, bias, gamma, beta, out);
}